// round 4
// baseline (speedup 1.0000x reference)
#include <cuda_runtime.h>
#include <cuda_bf16.h>
#include <stdint.h>

// loss = [ sum_{b,c,d} erfc(y) + 2*B*D - 2*sum_{b,d} erfc(y[b,label_b,d]) ] / (B*C)
// y = |W[c,d]-mu[b,d]| / (sqrt(2)*(std[b,d]+1e-8))
//
// erfc via A&S 7.1.25 (3-term, |err| <= 2.5e-5):
//   erfc(x) = (a1*t + a2*t^2 + a3*t^3) * exp(-x^2),  t = 1/(1+p*x)
// t computed WITHOUT MUFU.RCP: bit-trick initial guess + 2 Newton steps
// (rel err ~1e-5), leaving EX2 as the only MUFU op (1/element).
// Prefolded per-(b,d) constants: nm=-mu, nai=-p*iv, il=-log2e*iv^2.

#define BT 8          // batches per CTA (= warps)
#define CT 8          // classes per CTA (smem tile)
#define DCONST 512
#define CBLK 125      // C / CT
#define GRID_X (CBLK + 1)
#define GRID_Y 16
#define NCTAS (GRID_X * GRID_Y)   // 2016
#define NPART NCTAS

__device__ float g_partials[NPART];
__device__ unsigned int g_count = 0;   // self-resetting; 0 at every launch start

// ---------- f32x2 / MUFU primitives ----------
__device__ __forceinline__ uint64_t f2add(uint64_t a, uint64_t b) {
    uint64_t r; asm("add.rn.f32x2 %0,%1,%2;" : "=l"(r) : "l"(a), "l"(b)); return r;
}
__device__ __forceinline__ uint64_t f2mul(uint64_t a, uint64_t b) {
    uint64_t r; asm("mul.rn.f32x2 %0,%1,%2;" : "=l"(r) : "l"(a), "l"(b)); return r;
}
__device__ __forceinline__ uint64_t f2fma(uint64_t a, uint64_t b, uint64_t c) {
    uint64_t r; asm("fma.rn.f32x2 %0,%1,%2,%3;" : "=l"(r) : "l"(a), "l"(b), "l"(c)); return r;
}
__device__ __forceinline__ void unpk(uint64_t v, float& lo, float& hi) {
    asm("mov.b64 {%0,%1}, %2;" : "=f"(lo), "=f"(hi) : "l"(v));
}
__device__ __forceinline__ uint64_t pk(float lo, float hi) {
    uint64_t v; asm("mov.b64 %0, {%1,%2};" : "=l"(v) : "f"(lo), "f"(hi)); return v;
}
__device__ __forceinline__ uint64_t dup2(float v) {
    uint32_t u = __float_as_uint(v); return ((uint64_t)u << 32) | u;
}
__device__ __forceinline__ float rcp_f(float x) {
    float r; asm("rcp.approx.ftz.f32 %0,%1;" : "=f"(r) : "f"(x)); return r;
}
__device__ __forceinline__ float ex2_f(float x) {
    float r; asm("ex2.approx.ftz.f32 %0,%1;" : "=f"(r) : "f"(x)); return r;
}

#define AS_P  0.47047f
#define AS_A1 0.3480242f
#define AS_A2 (-0.0958798f)
#define AS_A3 0.7478556f
#define NLOG2E (-1.4426950408889634f)
#define ABS2MASK  0x7FFFFFFF7FFFFFFFULL
#define SIGN2MASK 0x8000000080000000ULL
#define RCP_MAGIC 0x7EF311C3u

// erfc of two elements, accumulated into acc (f32x2 lanes).
// nm = -mu pair, nai = -p*iv pair, il = -log2e*iv^2 pair.
__device__ __forceinline__ void erfc2_acc(uint64_t w2, uint64_t nm, uint64_t nai,
                                          uint64_t il, uint64_t& acc) {
    const uint64_t NEG1 = dup2(-1.0f);
    const uint64_t TWO2 = dup2(2.0f);
    const uint64_t A1 = dup2(AS_A1), A2 = dup2(AS_A2), A3 = dup2(AS_A3);

    uint64_t d   = f2add(w2, nm);               // w - mu              [FMA]
    uint64_t ad  = d & ABS2MASK;                 // |d|                 [ALU]
    uint64_t dd  = f2mul(d, d);                  // d^2                 [FMA]
    uint64_t ea  = f2mul(dd, il);                // -log2e * x^2        [FMA]
    uint64_t ndn = f2fma(nai, ad, NEG1);         // -(1 + p*x)          [FMA]

    // bit-trick reciprocal of dn = -ndn (flip sign bit, subtract from magic) [ALU]
    uint64_t dnb = ndn ^ SIGN2MASK;
    uint32_t r0l = RCP_MAGIC - (uint32_t)dnb;
    uint32_t r0h = RCP_MAGIC - (uint32_t)(dnb >> 32);
    uint64_t r = ((uint64_t)r0h << 32) | r0l;

    // two Newton steps: r = r*(2 - dn*r), with dn*r = -(ndn*r)        [4x FMA]
    uint64_t e = f2fma(ndn, r, TWO2);
    r = f2mul(r, e);
    e = f2fma(ndn, r, TWO2);
    uint64_t t = f2mul(r, e);

    uint64_t p  = f2fma(A3, t, A2);              //                     [FMA]
    p           = f2fma(p, t, A1);               //                     [FMA]
    uint64_t pt = f2mul(p, t);                   //                     [FMA]

    float ea0, ea1;
    unpk(ea, ea0, ea1);
    float e0 = ex2_f(ea0), e1 = ex2_f(ea1);      // MUFU.EX2 x2
    acc = f2fma(pt, pk(e0, e1), acc);            //                     [FMA]
}

// Preload one warp's per-(b,d) constants. Lane owns float4 units lane+32*i, i=0..3.
__device__ __forceinline__ void preload_bd(const float* __restrict__ mu,
                                           const float* __restrict__ stdv,
                                           int b, int lane,
                                           uint64_t* nm, uint64_t* nai, uint64_t* il) {
    const float4* mu4 = reinterpret_cast<const float4*>(mu + (size_t)b * DCONST);
    const float4* sd4 = reinterpret_cast<const float4*>(stdv + (size_t)b * DCONST);
#pragma unroll
    for (int i = 0; i < 4; i++) {
        float4 m = mu4[lane + 32 * i];
        float4 s = sd4[lane + 32 * i];
        float ivx = rcp_f(1.41421356237f * (s.x + 1e-8f));
        float ivy = rcp_f(1.41421356237f * (s.y + 1e-8f));
        float ivz = rcp_f(1.41421356237f * (s.z + 1e-8f));
        float ivw = rcp_f(1.41421356237f * (s.w + 1e-8f));
        nm[2 * i]      = pk(-m.x, -m.y);
        nm[2 * i + 1]  = pk(-m.z, -m.w);
        nai[2 * i]     = pk(-AS_P * ivx, -AS_P * ivy);
        nai[2 * i + 1] = pk(-AS_P * ivz, -AS_P * ivw);
        il[2 * i]      = pk(NLOG2E * ivx * ivx, NLOG2E * ivy * ivy);
        il[2 * i + 1]  = pk(NLOG2E * ivz * ivz, NLOG2E * ivw * ivw);
    }
}

__global__ __launch_bounds__(BT * 32, 2)
void erfc_main_kernel(const float* __restrict__ mu,
                      const float* __restrict__ stdv,
                      const float* __restrict__ w,
                      const int* __restrict__ label,
                      float* __restrict__ out,
                      int B, int C, int D) {
    __shared__ float sw[CT * DCONST];
    __shared__ float wsum[BT];
    __shared__ int s_is_last;

    const int warp = threadIdx.x >> 5;
    const int lane = threadIdx.x & 31;
    const int b = blockIdx.y * BT + warp;
    const bool is_label_cta = (blockIdx.x == CBLK);

    if (!is_label_cta) {
        const int c0 = blockIdx.x * CT;
        const float4* src = reinterpret_cast<const float4*>(w + (size_t)c0 * DCONST);
        float4* dst = reinterpret_cast<float4*>(sw);
        for (int i = threadIdx.x; i < CT * DCONST / 4; i += blockDim.x)
            dst[i] = src[i];
    }

    uint64_t nm[8], nai[8], il[8];
    preload_bd(mu, stdv, b, lane, nm, nai, il);

    if (!is_label_cta) __syncthreads();

    uint64_t acc = 0;  // (0.0f, 0.0f)

    if (!is_label_cta) {
        const ulonglong2* sw2 = reinterpret_cast<const ulonglong2*>(sw);
#pragma unroll
        for (int c = 0; c < CT; c++) {
#pragma unroll
            for (int i = 0; i < 4; i++) {
                ulonglong2 ww = sw2[c * (DCONST / 4) + lane + 32 * i];
                erfc2_acc(ww.x, nm[2 * i],     nai[2 * i],     il[2 * i],     acc);
                erfc2_acc(ww.y, nm[2 * i + 1], nai[2 * i + 1], il[2 * i + 1], acc);
            }
        }
    } else {
        int l = label[b];
        if (l < 0) l = 0;
        if (l >= CBLK * CT) l = CBLK * CT - 1;
        const ulonglong2* wr2 = reinterpret_cast<const ulonglong2*>(w + (size_t)l * DCONST);
#pragma unroll
        for (int i = 0; i < 4; i++) {
            ulonglong2 ww = wr2[lane + 32 * i];
            erfc2_acc(ww.x, nm[2 * i],     nai[2 * i],     il[2 * i],     acc);
            erfc2_acc(ww.y, nm[2 * i + 1], nai[2 * i + 1], il[2 * i + 1], acc);
        }
    }

    float alo, ahi;
    unpk(acc, alo, ahi);
    float a = alo + ahi;
#pragma unroll
    for (int o = 16; o > 0; o >>= 1)
        a += __shfl_xor_sync(0xFFFFFFFFu, a, o);
    if (lane == 0) wsum[warp] = a;
    __syncthreads();

    if (threadIdx.x == 0) {
        float s = 0.0f;
#pragma unroll
        for (int i = 0; i < BT; i++) s += wsum[i];
        if (is_label_cta) s *= -2.0f;
        g_partials[blockIdx.y * GRID_X + blockIdx.x] = s;
        __threadfence();
        unsigned int prev = atomicAdd(&g_count, 1u);
        s_is_last = (prev == NCTAS - 1) ? 1 : 0;
    }
    __syncthreads();

    // Last CTA: deterministic final reduction + output, then reset counter.
    if (s_is_last) {
        __threadfence();  // acquire: see all partials
        __shared__ double dsum[BT];
        double s = 0.0;
        for (int i = threadIdx.x; i < NPART; i += blockDim.x)
            s += (double)g_partials[i];
#pragma unroll
        for (int o = 16; o > 0; o >>= 1)
            s += __shfl_xor_sync(0xFFFFFFFFu, s, o);
        if (lane == 0) dsum[warp] = s;
        __syncthreads();
        if (threadIdx.x == 0) {
            double tt = 0.0;
#pragma unroll
            for (int i = 0; i < BT; i++) tt += dsum[i];
            out[0] = (float)((tt + 2.0 * (double)B * (double)D) /
                             ((double)B * (double)C));
            g_count = 0;  // restore invariant for next launch / graph replay
        }
    }
}

extern "C" void kernel_launch(void* const* d_in, const int* in_sizes, int n_in,
                              void* d_out, int out_size) {
    const float* mu    = (const float*)d_in[0];
    const float* stdv  = (const float*)d_in[1];
    const float* w     = (const float*)d_in[2];
    const int*   label = (const int*)d_in[3];

    const int B = in_sizes[3];            // 128
    const int D = in_sizes[0] / B;        // 512
    const int C = in_sizes[2] / D;        // 1000

    dim3 grid(GRID_X, GRID_Y);            // (126, 16)
    erfc_main_kernel<<<grid, BT * 32>>>(mu, stdv, w, label, (float*)d_out, B, C, D);
}

// round 5
// speedup vs baseline: 1.1535x; 1.1535x over previous
#include <cuda_runtime.h>
#include <cuda_bf16.h>
#include <stdint.h>

// loss = [ sum_{b,c,d} erfc(y) + 2*B*D - 2*sum_{b,d} erfc(y[b,label_b,d]) ] / (B*C)
// y = |W[c,d]-mu[b,d]| / (sqrt(2)*(std[b,d]+1e-8))
//
// erfc via A&S 7.1.25 (3-term, |err| <= 2.5e-5), t = 1/(1+p*x) computed with a
// bit-trick reciprocal + 2 Newton steps (FMA pipe), EX2 the only MUFU op.
// Per-(b,d) prefolded constants: nm=-mu, nai=-p*iv, il=-log2e*iv^2.
// Two-pass d-split keeps only half the constants live -> ~56 regs -> 4 CTAs/SM.

#define BT 8          // batches per CTA (= warps)
#define CT 8          // classes per CTA (smem tile)
#define DCONST 512
#define CBLK 125      // C / CT
#define GRID_X (CBLK + 1)
#define GRID_Y 16
#define NCTAS (GRID_X * GRID_Y)   // 2016
#define NPART NCTAS

__device__ float g_partials[NPART];
__device__ unsigned int g_count = 0;   // self-resetting; 0 at every launch start

// ---------- f32x2 / MUFU primitives ----------
__device__ __forceinline__ uint64_t f2add(uint64_t a, uint64_t b) {
    uint64_t r; asm("add.rn.f32x2 %0,%1,%2;" : "=l"(r) : "l"(a), "l"(b)); return r;
}
__device__ __forceinline__ uint64_t f2mul(uint64_t a, uint64_t b) {
    uint64_t r; asm("mul.rn.f32x2 %0,%1,%2;" : "=l"(r) : "l"(a), "l"(b)); return r;
}
__device__ __forceinline__ uint64_t f2fma(uint64_t a, uint64_t b, uint64_t c) {
    uint64_t r; asm("fma.rn.f32x2 %0,%1,%2,%3;" : "=l"(r) : "l"(a), "l"(b), "l"(c)); return r;
}
__device__ __forceinline__ void unpk(uint64_t v, float& lo, float& hi) {
    asm("mov.b64 {%0,%1}, %2;" : "=f"(lo), "=f"(hi) : "l"(v));
}
__device__ __forceinline__ uint64_t pk(float lo, float hi) {
    uint64_t v; asm("mov.b64 %0, {%1,%2};" : "=l"(v) : "f"(lo), "f"(hi)); return v;
}
__device__ __forceinline__ uint64_t dup2(float v) {
    uint32_t u = __float_as_uint(v); return ((uint64_t)u << 32) | u;
}
__device__ __forceinline__ float rcp_f(float x) {
    float r; asm("rcp.approx.ftz.f32 %0,%1;" : "=f"(r) : "f"(x)); return r;
}
__device__ __forceinline__ float ex2_f(float x) {
    float r; asm("ex2.approx.ftz.f32 %0,%1;" : "=f"(r) : "f"(x)); return r;
}

#define AS_P  0.47047f
#define AS_A1 0.3480242f
#define AS_A2 (-0.0958798f)
#define AS_A3 0.7478556f
#define NLOG2E (-1.4426950408889634f)
#define ABS2MASK  0x7FFFFFFF7FFFFFFFULL
// rcp magic, pre-folded with the sign flip of -(1+p*x):
// 0xFEF311C3 - bits(-dn) == 0x7EF311C3 - bits(dn), no borrow into bit 31.
#define RCP_MAGIC_NEG 0xFEF311C3u

// erfc of two elements, accumulated into acc (f32x2 lanes).
__device__ __forceinline__ void erfc2_acc(uint64_t w2, uint64_t nm, uint64_t nai,
                                          uint64_t il, uint64_t& acc) {
    const uint64_t NEG1 = dup2(-1.0f);
    const uint64_t TWO2 = dup2(2.0f);
    const uint64_t A1 = dup2(AS_A1), A2 = dup2(AS_A2), A3 = dup2(AS_A3);

    uint64_t d   = f2add(w2, nm);                // w - mu              [FMA]
    uint64_t ad  = d & ABS2MASK;                 // |d|                 [ALU]
    uint64_t dd  = f2mul(d, d);                  // d^2                 [FMA]
    uint64_t ea  = f2mul(dd, il);                // -log2e * x^2        [FMA]
    uint64_t ndn = f2fma(nai, ad, NEG1);         // -(1 + p*x)          [FMA]

    // bit-trick reciprocal of dn = -ndn, sign folded into magic        [2 ALU]
    uint32_t r0l = RCP_MAGIC_NEG - (uint32_t)ndn;
    uint32_t r0h = RCP_MAGIC_NEG - (uint32_t)(ndn >> 32);
    uint64_t r = ((uint64_t)r0h << 32) | r0l;

    // two Newton steps: r = r*(2 - dn*r) = r*(2 + ndn*r)              [4x FMA]
    uint64_t e = f2fma(ndn, r, TWO2);
    r = f2mul(r, e);
    e = f2fma(ndn, r, TWO2);
    uint64_t t = f2mul(r, e);

    uint64_t p  = f2fma(A3, t, A2);              //                     [FMA]
    p           = f2fma(p, t, A1);               //                     [FMA]
    uint64_t pt = f2mul(p, t);                   //                     [FMA]

    float ea0, ea1;
    unpk(ea, ea0, ea1);
    float e0 = ex2_f(ea0), e1 = ex2_f(ea1);      // MUFU.EX2 x2
    acc = f2fma(pt, pk(e0, e1), acc);            //                     [FMA]
}

// Preload constants for one d-half (8 elements/lane = 2 float4 units).
// unit u = lane + 32*(2*half + j), j in {0,1}; pairs 2j, 2j+1.
__device__ __forceinline__ void preload_half(const float* __restrict__ mu,
                                             const float* __restrict__ stdv,
                                             int b, int lane, int half,
                                             uint64_t* nm, uint64_t* nai, uint64_t* il) {
    const float4* mu4 = reinterpret_cast<const float4*>(mu + (size_t)b * DCONST);
    const float4* sd4 = reinterpret_cast<const float4*>(stdv + (size_t)b * DCONST);
#pragma unroll
    for (int j = 0; j < 2; j++) {
        int u = lane + 32 * (2 * half + j);
        float4 m = mu4[u];
        float4 s = sd4[u];
        float ivx = rcp_f(1.41421356237f * (s.x + 1e-8f));
        float ivy = rcp_f(1.41421356237f * (s.y + 1e-8f));
        float ivz = rcp_f(1.41421356237f * (s.z + 1e-8f));
        float ivw = rcp_f(1.41421356237f * (s.w + 1e-8f));
        nm[2 * j]      = pk(-m.x, -m.y);
        nm[2 * j + 1]  = pk(-m.z, -m.w);
        nai[2 * j]     = pk(-AS_P * ivx, -AS_P * ivy);
        nai[2 * j + 1] = pk(-AS_P * ivz, -AS_P * ivw);
        il[2 * j]      = pk(NLOG2E * ivx * ivx, NLOG2E * ivy * ivy);
        il[2 * j + 1]  = pk(NLOG2E * ivz * ivz, NLOG2E * ivw * ivw);
    }
}

__global__ __launch_bounds__(BT * 32, 4)
void erfc_main_kernel(const float* __restrict__ mu,
                      const float* __restrict__ stdv,
                      const float* __restrict__ w,
                      const int* __restrict__ label,
                      float* __restrict__ out,
                      int B, int C, int D) {
    __shared__ float sw[CT * DCONST];
    __shared__ float wsum[BT];
    __shared__ int s_is_last;

    const int warp = threadIdx.x >> 5;
    const int lane = threadIdx.x & 31;
    const int b = blockIdx.y * BT + warp;
    const bool is_label_cta = (blockIdx.x == CBLK);

    int lrow = 0;
    if (is_label_cta) {
        lrow = label[b];
        if (lrow < 0) lrow = 0;
        if (lrow >= CBLK * CT) lrow = CBLK * CT - 1;
    } else {
        const int c0 = blockIdx.x * CT;
        const float4* src = reinterpret_cast<const float4*>(w + (size_t)c0 * DCONST);
        float4* dst = reinterpret_cast<float4*>(sw);
        for (int i = threadIdx.x; i < CT * DCONST / 4; i += blockDim.x)
            dst[i] = src[i];
        __syncthreads();
    }

    uint64_t acc0 = 0, acc1 = 0;

#pragma unroll
    for (int half = 0; half < 2; half++) {
        uint64_t nm[4], nai[4], il[4];
        preload_half(mu, stdv, b, lane, half, nm, nai, il);

        if (!is_label_cta) {
            const ulonglong2* sw2 = reinterpret_cast<const ulonglong2*>(sw);
#pragma unroll
            for (int c = 0; c < CT; c++) {
#pragma unroll
                for (int j = 0; j < 2; j++) {
                    ulonglong2 ww = sw2[c * (DCONST / 4) + lane + 32 * (2 * half + j)];
                    erfc2_acc(ww.x, nm[2 * j],     nai[2 * j],     il[2 * j],     acc0);
                    erfc2_acc(ww.y, nm[2 * j + 1], nai[2 * j + 1], il[2 * j + 1], acc1);
                }
            }
        } else {
            const ulonglong2* wr2 =
                reinterpret_cast<const ulonglong2*>(w + (size_t)lrow * DCONST);
#pragma unroll
            for (int j = 0; j < 2; j++) {
                ulonglong2 ww = wr2[lane + 32 * (2 * half + j)];
                erfc2_acc(ww.x, nm[2 * j],     nai[2 * j],     il[2 * j],     acc0);
                erfc2_acc(ww.y, nm[2 * j + 1], nai[2 * j + 1], il[2 * j + 1], acc1);
            }
        }
    }

    uint64_t acc = f2add(acc0, acc1);
    float alo, ahi;
    unpk(acc, alo, ahi);
    float a = alo + ahi;
#pragma unroll
    for (int o = 16; o > 0; o >>= 1)
        a += __shfl_xor_sync(0xFFFFFFFFu, a, o);
    if (lane == 0) wsum[warp] = a;
    __syncthreads();

    if (threadIdx.x == 0) {
        float s = 0.0f;
#pragma unroll
        for (int i = 0; i < BT; i++) s += wsum[i];
        if (is_label_cta) s *= -2.0f;
        g_partials[blockIdx.y * GRID_X + blockIdx.x] = s;
        __threadfence();
        unsigned int prev = atomicAdd(&g_count, 1u);
        s_is_last = (prev == NCTAS - 1) ? 1 : 0;
    }
    __syncthreads();

    // Last CTA: deterministic final reduction + output, then reset counter.
    if (s_is_last) {
        __threadfence();  // acquire: see all partials
        __shared__ double dsum[BT];
        double s = 0.0;
        for (int i = threadIdx.x; i < NPART; i += blockDim.x)
            s += (double)g_partials[i];
#pragma unroll
        for (int o = 16; o > 0; o >>= 1)
            s += __shfl_xor_sync(0xFFFFFFFFu, s, o);
        if (lane == 0) dsum[warp] = s;
        __syncthreads();
        if (threadIdx.x == 0) {
            double tt = 0.0;
#pragma unroll
            for (int i = 0; i < BT; i++) tt += dsum[i];
            out[0] = (float)((tt + 2.0 * (double)B * (double)D) /
                             ((double)B * (double)C));
            g_count = 0;  // restore invariant for next launch / graph replay
        }
    }
}

extern "C" void kernel_launch(void* const* d_in, const int* in_sizes, int n_in,
                              void* d_out, int out_size) {
    const float* mu    = (const float*)d_in[0];
    const float* stdv  = (const float*)d_in[1];
    const float* w     = (const float*)d_in[2];
    const int*   label = (const int*)d_in[3];

    const int B = in_sizes[3];            // 128
    const int D = in_sizes[0] / B;        // 512
    const int C = in_sizes[2] / D;        // 1000

    dim3 grid(GRID_X, GRID_Y);            // (126, 16)
    erfc_main_kernel<<<grid, BT * 32>>>(mu, stdv, w, label, (float*)d_out, B, C, D);
}